// round 16
// baseline (speedup 1.0000x reference)
#include <cuda_runtime.h>
#include <cuda_bf16.h>
#include <math.h>

// Problem dims (fixed by the reference)
#define BB 16
#define TT 4096
#define HH 1024
#define KK 128
#define VV 128
#define OO 128
#define PP 512            // 3K + V
#define MM (BB * TT)      // 65536

// Scratch (static device globals: allocation-free, graph-capturable)
__device__ float g_qkgv[(size_t)BB * TT * PP];   // 128 MB activated projections
__device__ float g_obuf[(size_t)BB * TT * VV];   // 32 MB pre-projection readout
__device__ float g_cdump[(size_t)BB * KK * VV];  // fallback c_final sink
__device__ __nv_bfloat16 g_ahi[(size_t)MM * HH]; // hidden split hi
__device__ __nv_bfloat16 g_alo[(size_t)MM * HH]; // hidden split lo
__device__ __nv_bfloat16 g_whi[(size_t)PP * HH];
__device__ __nv_bfloat16 g_wlo[(size_t)PP * HH];

typedef unsigned long long ull;

// ---------------------------------------------------------------------------
// small PTX helpers
// ---------------------------------------------------------------------------
__device__ __forceinline__ unsigned smem_u32(const void* p) {
    return (unsigned)__cvta_generic_to_shared(p);
}
__device__ __forceinline__ void cp16(void* dst, const void* src) {
    asm volatile("cp.async.cg.shared.global [%0], [%1], 16;\n"
                 :: "r"(smem_u32(dst)), "l"(src));
}
__device__ __forceinline__ void cp_commit() {
    asm volatile("cp.async.commit_group;\n");
}
__device__ __forceinline__ void cp_wait1() {
    asm volatile("cp.async.wait_group 1;\n");
}
__device__ __forceinline__ void ldsm4(unsigned r[4], const void* p) {
    unsigned a = smem_u32(p);
    asm volatile("ldmatrix.sync.aligned.m8n8.x4.shared.b16 {%0,%1,%2,%3}, [%4];\n"
                 : "=r"(r[0]), "=r"(r[1]), "=r"(r[2]), "=r"(r[3]) : "r"(a));
}
__device__ __forceinline__ void mma16816(float d[4], const unsigned a[4],
                                         unsigned b0, unsigned b1) {
    asm volatile("mma.sync.aligned.m16n8k16.row.col.f32.bf16.bf16.f32 "
                 "{%0,%1,%2,%3}, {%4,%5,%6,%7}, {%8,%9}, {%0,%1,%2,%3};\n"
                 : "+f"(d[0]), "+f"(d[1]), "+f"(d[2]), "+f"(d[3])
                 : "r"(a[0]), "r"(a[1]), "r"(a[2]), "r"(a[3]), "r"(b0), "r"(b1));
}
__device__ __forceinline__ unsigned short bfbits(__nv_bfloat16 h) {
    return ((__nv_bfloat16_raw)h).x;
}

// ---------------------------------------------------------------------------
// fp32 -> (hi, lo) bf16 split. x = hi + lo + O(2^-16 |x|).
// ---------------------------------------------------------------------------
__global__ __launch_bounds__(256) void cvt_hilo(
    const float* __restrict__ x, __nv_bfloat16* __restrict__ hi,
    __nv_bfloat16* __restrict__ lo, int n4)
{
    int i = blockIdx.x * blockDim.x + threadIdx.x;
    if (i >= n4) return;
    float4 xv = ((const float4*)x)[i];
    float xs[4] = {xv.x, xv.y, xv.z, xv.w};
    unsigned short hb[4], lb[4];
#pragma unroll
    for (int j = 0; j < 4; ++j) {
        __nv_bfloat16 h = __float2bfloat16(xs[j]);
        float r = xs[j] - __bfloat162float(h);   // exact residual
        __nv_bfloat16 l = __float2bfloat16(r);
        hb[j] = bfbits(h);
        lb[j] = bfbits(l);
    }
    uint2 uh = make_uint2(hb[0] | ((unsigned)hb[1] << 16),
                          hb[2] | ((unsigned)hb[3] << 16));
    uint2 ul = make_uint2(lb[0] | ((unsigned)lb[1] << 16),
                          lb[2] | ((unsigned)lb[3] << 16));
    ((uint2*)hi)[i] = uh;
    ((uint2*)lo)[i] = ul;
}

// ---------------------------------------------------------------------------
// GEMM1 v2 (round-13, unchanged): qkgv[M,512] = act( A @ W^T + bias )
// bf16 hi/lo split, 3-term mma.sync, CTA tile 128m x 256n, BK=32,
// 8 warps (4m x 2n), warp tile 32x128, cp.async 3-stage ring.
// ---------------------------------------------------------------------------
#define G1_STRIDE 40                       // bf16 per smem row (32 + 8 pad)
#define G1_PLANE_A (128 * G1_STRIDE)       // 5120 bf16
#define G1_PLANE_W (256 * G1_STRIDE)       // 10240 bf16
#define G1_STAGE  (2 * G1_PLANE_A + 2 * G1_PLANE_W)   // 30720 bf16
#define G1_SMEM   (3 * G1_STAGE * 2)       // 184320 B

__global__ __launch_bounds__(256) void gemm1_mma(
    const __nv_bfloat16* __restrict__ Ah, const __nv_bfloat16* __restrict__ Al,
    const __nv_bfloat16* __restrict__ Wh, const __nv_bfloat16* __restrict__ Wl,
    const float* __restrict__ bias, float* __restrict__ C)
{
    extern __shared__ __nv_bfloat16 sm[];
    const int tid  = threadIdx.x;
    const int m0   = blockIdx.y << 7;
    const int n0   = blockIdx.x << 8;      // 256-wide n tile
    const int lane = tid & 31;
    const int warp = tid >> 5;
    const int wm   = (warp & 3) << 5;      // warp m offset (0..96)
    const int wn   = (warp >> 2) << 7;     // warp n offset (0 or 128)

    const __nv_bfloat16* srcs[4] = {
        Ah + (size_t)m0 * HH, Al + (size_t)m0 * HH,
        Wh + (size_t)n0 * HH, Wl + (size_t)n0 * HH };
    const int poff[4]  = {0, G1_PLANE_A, 2 * G1_PLANE_A, 2 * G1_PLANE_A + G1_PLANE_W};

    // load one k32 block (3072 16B chunks) into stage st
    auto issue = [&](int kt, int st) {
        __nv_bfloat16* sb = sm + st * G1_STAGE;
#pragma unroll
        for (int h = 0; h < 12; ++h) {
            int c    = tid + (h << 8);           // 0..3071
            int grow = c >> 2;                   // 0..767
            int col  = (c & 3) << 3;
            int p    = (grow < 256) ? (grow >> 7) : (2 + ((grow - 256) >> 8));
            int r    = (grow < 256) ? (grow & 127) : ((grow - 256) & 255);
            cp16(sb + poff[p] + r * G1_STRIDE + col,
                 srcs[p] + (size_t)r * HH + kt * 32 + col);
        }
        cp_commit();
    };

    float acc[2][16][4];
#pragma unroll
    for (int im = 0; im < 2; ++im)
#pragma unroll
        for (int j = 0; j < 16; ++j)
#pragma unroll
            for (int r = 0; r < 4; ++r) acc[im][j][r] = 0.f;

    issue(0, 0);
    issue(1, 1);

    const int arow  = lane & 15;
    const int acolb = (lane >> 4) << 3;
    const int brow  = ((lane & 16) >> 1) + (lane & 7);
    const int bcolb = ((lane >> 3) & 1) << 3;

    const int nk = HH / 32;                // 32
    for (int kt = 0; kt < nk; ++kt) {
        cp_wait1();
        __syncthreads();
        const __nv_bfloat16* st  = sm + (kt % 3) * G1_STAGE;
        const __nv_bfloat16* sAh = st;
        const __nv_bfloat16* sAl = st + G1_PLANE_A;
        const __nv_bfloat16* sWh = st + 2 * G1_PLANE_A;
        const __nv_bfloat16* sWl = st + 2 * G1_PLANE_A + G1_PLANE_W;
#pragma unroll
        for (int ks = 0; ks < 2; ++ks) {
            const int ko = ks << 4;
            unsigned aH[2][4], aL[2][4];
#pragma unroll
            for (int im = 0; im < 2; ++im) {
                int r = wm + (im << 4) + arow;
                ldsm4(aH[im], sAh + r * G1_STRIDE + ko + acolb);
                ldsm4(aL[im], sAl + r * G1_STRIDE + ko + acolb);
            }
#pragma unroll
            for (int ng = 0; ng < 8; ++ng) {
                int r = wn + (ng << 4) + brow;
                unsigned bh[4], bl[4];
                ldsm4(bh, sWh + r * G1_STRIDE + ko + bcolb);
                ldsm4(bl, sWl + r * G1_STRIDE + ko + bcolb);
#pragma unroll
                for (int im = 0; im < 2; ++im) {
                    mma16816(acc[im][ng * 2],     aH[im], bh[0], bh[1]);
                    mma16816(acc[im][ng * 2 + 1], aH[im], bh[2], bh[3]);
                    mma16816(acc[im][ng * 2],     aH[im], bl[0], bl[1]);
                    mma16816(acc[im][ng * 2 + 1], aH[im], bl[2], bl[3]);
                    mma16816(acc[im][ng * 2],     aL[im], bh[0], bh[1]);
                    mma16816(acc[im][ng * 2 + 1], aL[im], bh[2], bh[3]);
                }
            }
        }
        if (kt + 2 < nk) issue(kt + 2, (kt + 2) % 3);
        else             cp_commit();
    }

    // epilogue: bias + activation (block 0:q id, 1:k sig, 2:g sig, 3:v tanh)
    const int nblk = (n0 + wn) >> 7;
    const int act  = (nblk == 0) ? 0 : ((nblk == 3) ? 2 : 1);
    const int r0     = m0 + wm + (lane >> 2);
    const int c0base = n0 + wn + ((lane & 3) << 1);
#pragma unroll
    for (int j = 0; j < 16; ++j) {
        int col = c0base + (j << 3);
        float b0 = bias[col], b1 = bias[col + 1];
#pragma unroll
        for (int im = 0; im < 2; ++im) {
            int rb = r0 + (im << 4);
            float v0 = acc[im][j][0] + b0, v1 = acc[im][j][1] + b1;
            float v2 = acc[im][j][2] + b0, v3 = acc[im][j][3] + b1;
            if (act == 1) {
                v0 = 1.f / (1.f + __expf(-v0)); v1 = 1.f / (1.f + __expf(-v1));
                v2 = 1.f / (1.f + __expf(-v2)); v3 = 1.f / (1.f + __expf(-v3));
            } else if (act == 2) {
                v0 = tanhf(v0); v1 = tanhf(v1); v2 = tanhf(v2); v3 = tanhf(v3);
            }
            *(float2*)(C + (size_t)rb * PP + col)       = make_float2(v0, v1);
            *(float2*)(C + (size_t)(rb + 8) * PP + col) = make_float2(v2, v3);
        }
    }
}

// ---------------------------------------------------------------------------
// Sequential scan v6: 2 independent CTAs per SM (latency hiding without
// crossbar blowup). Grid (batch=16, v-tile=16) = 256 CTAs, 128 threads.
// v-tile = 8. Warp w owns v-pair {v0+2w, v0+2w+1}; lane l owns k's
// {4l..4l+3} (contiguous float4, conflict-free). State c[4][2].
// Per-CTA crossbar/step: 3 ops x 4 phases x 4 warps = 48 phases; per SM
// (2 CTAs) ~96/step-pair, under the 128B/cyc ceiling. The 2 CTAs have
// independent barriers -> stalls decouple (unlike one 8-warp CTA).
// 8-step groups, 3-ring cp.async, refill right after the top barrier.
// ---------------------------------------------------------------------------
#define SC_GROUPS 3
#define SC_GS     8                        // steps per group
#define SC_STAGES (SC_GROUPS * SC_GS)      // 24
#define SC_ROW    392                      // q:128 | k:128 | g:128 | v-tile:8

__global__ __launch_bounds__(128) void scan_kernel(
    const float* __restrict__ qkgv, float* __restrict__ obuf,
    float* __restrict__ cfin)
{
    const int b   = blockIdx.x;
    const int v0  = blockIdx.y << 3;     // v-tile base (8 wide)
    const int tid = threadIdx.x;
    const int w   = tid >> 5;            // warp: v-pair {2w, 2w+1}
    const int l   = tid & 31;            // lane: k's 4l..4l+3
    const int k0  = l << 2;
    const int vp  = w << 1;              // v-pair base within tile

    __shared__ float s[SC_STAGES][SC_ROW];

    const float* base = qkgv + (size_t)b * TT * PP;
    float* ob = obuf + (size_t)b * TT * VV + v0 + vp;

    float c[4][2];                       // c[k_sub][v_sub]
#pragma unroll
    for (int i = 0; i < 4; ++i) { c[i][0] = 0.f; c[i][1] = 0.f; }

    // 98 copy threads x 16B per step (96 for q/k/g, 2 for the 8-wide v-tile)
    const bool cpr = (tid < 98);
    const int goff = (tid < 96) ? (tid << 2) : (384 + v0 + ((tid - 96) << 2));
    const int soff = (tid < 96) ? (tid << 2) : (384 + ((tid - 96) << 2));

    auto issue_group = [&](int g) {
        if (cpr) {
            const int sb = (g % SC_GROUPS) * SC_GS;
            const float* p = base + (size_t)(g * SC_GS) * PP + goff;
#pragma unroll
            for (int i = 0; i < SC_GS; ++i)
                cp16(&s[sb + i][soff], p + (size_t)i * PP);
        }
        cp_commit();
    };

    issue_group(0);
    issue_group(1);

    const int NG = TT / SC_GS;           // 512 groups
    for (int g = 0; g < NG; ++g) {
        cp_wait1();                      // group g complete
        __syncthreads();

        // refill: group g+2 -> slots of group g-1 (readers passed barrier)
        if (g + 2 < NG) issue_group(g + 2);
        else            cp_commit();

        const int sb = (g % SC_GROUPS) * SC_GS;

        float a0[SC_GS], a1[SC_GS];
#pragma unroll
        for (int i = 0; i < SC_GS; ++i) {
            const float* st = s[sb + i];
            float4 q  = *(const float4*)&st[k0];
            float4 kk = *(const float4*)&st[128 + k0];
            float4 gg = *(const float4*)&st[256 + k0];
            float2 vv = *(const float2*)&st[384 + vp];   // octet-broadcast

            c[0][0] = fmaf(c[0][0], gg.x, kk.x * vv.x);
            c[0][1] = fmaf(c[0][1], gg.x, kk.x * vv.y);
            c[1][0] = fmaf(c[1][0], gg.y, kk.y * vv.x);
            c[1][1] = fmaf(c[1][1], gg.y, kk.y * vv.y);
            c[2][0] = fmaf(c[2][0], gg.z, kk.z * vv.x);
            c[2][1] = fmaf(c[2][1], gg.z, kk.z * vv.y);
            c[3][0] = fmaf(c[3][0], gg.w, kk.w * vv.x);
            c[3][1] = fmaf(c[3][1], gg.w, kk.w * vv.y);

            float p0 = c[0][0] * q.x;
            float p1 = c[0][1] * q.x;
            p0 = fmaf(c[1][0], q.y, p0);  p1 = fmaf(c[1][1], q.y, p1);
            p0 = fmaf(c[2][0], q.z, p0);  p1 = fmaf(c[2][1], q.z, p1);
            p0 = fmaf(c[3][0], q.w, p0);  p1 = fmaf(c[3][1], q.w, p1);
            a0[i] = p0;  a1[i] = p1;
        }

        // 16 interleaved full-warp butterflies (reduce over all 128 k)
#pragma unroll
        for (int d = 1; d < 32; d <<= 1) {
#pragma unroll
            for (int i = 0; i < SC_GS; ++i) {
                a0[i] += __shfl_xor_sync(0xffffffffu, a0[i], d);
                a1[i] += __shfl_xor_sync(0xffffffffu, a1[i], d);
            }
        }
        if (l == 0) {
            const size_t t8 = (size_t)(g * SC_GS) * VV;
#pragma unroll
            for (int i = 0; i < SC_GS; ++i)
                *(float2*)&ob[t8 + (size_t)i * VV] = make_float2(a0[i], a1[i]);
        }
    }

    // c_final: (B, K, V). Thread owns k rows 4l..4l+3, v cols v0+vp..+1.
#pragma unroll
    for (int i = 0; i < 4; ++i)
        *(float2*)&cfin[((size_t)b * KK + (k0 + i)) * VV + v0 + vp] =
            make_float2(c[i][0], c[i][1]);
}

// ---------------------------------------------------------------------------
// GEMM2 (small): fp32 SIMT TN GEMM, 128x128 tile, BK=16.
// ---------------------------------------------------------------------------
__global__ __launch_bounds__(256) void gemm_tn(
    const float* __restrict__ A, const float* __restrict__ W,
    const float* __restrict__ bias, float* __restrict__ C,
    int M, int N, int Kd)
{
    __shared__ float As[2][16][136];
    __shared__ float Bs[2][16][136];

    const int tid = threadIdx.x;
    const int m0 = blockIdx.y << 7;
    const int n0 = blockIdx.x << 7;
    const int lr = tid >> 1;
    const int lc = (tid & 1) << 3;

    const float* Aptr = A + (size_t)(m0 + lr) * Kd + lc;
    const float* Wptr = W + (size_t)(n0 + lr) * Kd + lc;

    {
        float4 a0 = *(const float4*)Aptr;
        float4 a1 = *(const float4*)(Aptr + 4);
        float4 b0 = *(const float4*)Wptr;
        float4 b1 = *(const float4*)(Wptr + 4);
#pragma unroll
        for (int cc = 0; cc < 4; ++cc) {
            As[0][lc + cc][lr]     = ((const float*)&a0)[cc];
            As[0][lc + 4 + cc][lr] = ((const float*)&a1)[cc];
            Bs[0][lc + cc][lr]     = ((const float*)&b0)[cc];
            Bs[0][lc + 4 + cc][lr] = ((const float*)&b1)[cc];
        }
    }
    __syncthreads();

    const int ty  = tid >> 4;
    const int tx  = tid & 15;
    const int ar0 = ty << 2;
    const int bc0 = tx << 2;

    float acc[8][8];
#pragma unroll
    for (int i = 0; i < 8; ++i)
#pragma unroll
        for (int j = 0; j < 8; ++j) acc[i][j] = 0.f;

    const int nk = Kd >> 4;
    for (int kt = 0; kt < nk; ++kt) {
        const int buf = kt & 1;
        float4 pa0, pa1, pb0, pb1;
        const bool pf = (kt + 1) < nk;
        if (pf) {
            const float* Ap = Aptr + ((kt + 1) << 4);
            const float* Wp = Wptr + ((kt + 1) << 4);
            pa0 = *(const float4*)Ap;  pa1 = *(const float4*)(Ap + 4);
            pb0 = *(const float4*)Wp;  pb1 = *(const float4*)(Wp + 4);
        }
#pragma unroll
        for (int kk = 0; kk < 16; ++kk) {
            float4 a0 = *(const float4*)&As[buf][kk][ar0];
            float4 a1 = *(const float4*)&As[buf][kk][64 + ar0];
            float4 b0 = *(const float4*)&Bs[buf][kk][bc0];
            float4 b1 = *(const float4*)&Bs[buf][kk][64 + bc0];
            float af[8] = {a0.x,a0.y,a0.z,a0.w,a1.x,a1.y,a1.z,a1.w};
            float bf[8] = {b0.x,b0.y,b0.z,b0.w,b1.x,b1.y,b1.z,b1.w};
#pragma unroll
            for (int i = 0; i < 8; ++i)
#pragma unroll
                for (int j = 0; j < 8; ++j)
                    acc[i][j] = fmaf(af[i], bf[j], acc[i][j]);
        }
        if (pf) {
            const int nb = buf ^ 1;
#pragma unroll
            for (int cc = 0; cc < 4; ++cc) {
                As[nb][lc + cc][lr]     = ((const float*)&pa0)[cc];
                As[nb][lc + 4 + cc][lr] = ((const float*)&pa1)[cc];
                Bs[nb][lc + cc][lr]     = ((const float*)&pb0)[cc];
                Bs[nb][lc + 4 + cc][lr] = ((const float*)&pb1)[cc];
            }
        }
        __syncthreads();
    }

    float bv[8];
#pragma unroll
    for (int j = 0; j < 8; ++j) {
        int n = n0 + ((j < 4) ? (bc0 + j) : (64 + bc0 + (j - 4)));
        bv[j] = bias[n];
    }
#pragma unroll
    for (int i = 0; i < 8; ++i) {
        int m = m0 + ((i < 4) ? (ar0 + i) : (64 + ar0 + (i - 4)));
        float o[8];
#pragma unroll
        for (int j = 0; j < 8; ++j) o[j] = acc[i][j] + bv[j];
        float* cp = C + (size_t)m * N + n0;
        *(float4*)(cp + bc0)      = make_float4(o[0], o[1], o[2], o[3]);
        *(float4*)(cp + 64 + bc0) = make_float4(o[4], o[5], o[6], o[7]);
    }
}

// ---------------------------------------------------------------------------
extern "C" void kernel_launch(void* const* d_in, const int* in_sizes, int n_in,
                              void* d_out, int out_size)
{
    const float* hidden = (const float*)d_in[0];  // (B,T,H)
    const float* W_proj = (const float*)d_in[1];  // (3K+V, H)
    const float* b_proj = (const float*)d_in[2];  // (3K+V,)
    const float* W_out  = (const float*)d_in[3];  // (O, V)
    const float* b_out  = (const float*)d_in[4];  // (O,)
    float* out = (float*)d_out;

    float *qkgv, *obuf, *cdump;
    __nv_bfloat16 *ahi, *alo, *whi, *wlo;
    cudaGetSymbolAddress((void**)&qkgv,  g_qkgv);
    cudaGetSymbolAddress((void**)&obuf,  g_obuf);
    cudaGetSymbolAddress((void**)&cdump, g_cdump);
    cudaGetSymbolAddress((void**)&ahi,   g_ahi);
    cudaGetSymbolAddress((void**)&alo,   g_alo);
    cudaGetSymbolAddress((void**)&whi,   g_whi);
    cudaGetSymbolAddress((void**)&wlo,   g_wlo);

    const size_t out_main = (size_t)BB * TT * OO;
    const size_t out_full = out_main + (size_t)BB * KK * VV;
    float* cfin = ((size_t)out_size >= out_full) ? (out + out_main) : cdump;

    // 0) fp32 -> bf16 hi/lo splits
    {
        int n4 = (MM * HH) / 4;                     // 16,777,216
        cvt_hilo<<<(n4 + 255) / 256, 256>>>(hidden, ahi, alo, n4);
        int w4 = (PP * HH) / 4;                     // 131,072
        cvt_hilo<<<(w4 + 255) / 256, 256>>>(W_proj, whi, wlo, w4);
    }
    // 1) fused projection GEMM (mma.sync, 3-term bf16 split, N-fused tiles)
    {
        cudaFuncSetAttribute(gemm1_mma,
                             cudaFuncAttributeMaxDynamicSharedMemorySize, G1_SMEM);
        dim3 grid(PP / 256, MM / 128);              // (2, 512)
        gemm1_mma<<<grid, 256, G1_SMEM>>>(ahi, alo, whi, wlo, b_proj, qkgv);
    }
    // 2) sequential gated fast-weight scan (2 CTAs/SM, v-tile 8)
    {
        dim3 grid(BB, VV / 8);                      // (16, 16) = 256 CTAs
        scan_kernel<<<grid, 128>>>(qkgv, obuf, cfin);
    }
    // 3) output projection
    {
        dim3 grid(OO / 128, MM / 128);              // (1, 512)
        gemm_tn<<<grid, 256>>>(obuf, W_out, b_out, out, MM, OO, VV);
    }
}

// round 17
// speedup vs baseline: 1.1044x; 1.1044x over previous
#include <cuda_runtime.h>
#include <cuda_bf16.h>
#include <math.h>

// Problem dims (fixed by the reference)
#define BB 16
#define TT 4096
#define HH 1024
#define KK 128
#define VV 128
#define OO 128
#define PP 512            // 3K + V
#define MM (BB * TT)      // 65536
#define LS 128            // scan segment length
#define NSEG (TT / LS)    // 32

// Scratch (static device globals: allocation-free, graph-capturable)
__device__ float g_qkgv[(size_t)BB * TT * PP];   // 128 MB activated projections
__device__ float g_obuf[(size_t)BB * TT * VV];   // 32 MB pre-projection readout
__device__ float g_cdump[(size_t)BB * KK * VV];  // fallback c_final sink
__device__ __nv_bfloat16 g_ahi[(size_t)MM * HH]; // hidden hi; REUSED by scan as P/S/C0/Gtot
__device__ __nv_bfloat16 g_alo[(size_t)MM * HH]; // hidden split lo
__device__ __nv_bfloat16 g_whi[(size_t)PP * HH];
__device__ __nv_bfloat16 g_wlo[(size_t)PP * HH];

typedef unsigned long long ull;

// ---------------------------------------------------------------------------
// small PTX helpers
// ---------------------------------------------------------------------------
__device__ __forceinline__ unsigned smem_u32(const void* p) {
    return (unsigned)__cvta_generic_to_shared(p);
}
__device__ __forceinline__ void cp16(void* dst, const void* src) {
    asm volatile("cp.async.cg.shared.global [%0], [%1], 16;\n"
                 :: "r"(smem_u32(dst)), "l"(src));
}
__device__ __forceinline__ void cp_commit() {
    asm volatile("cp.async.commit_group;\n");
}
__device__ __forceinline__ void cp_wait1() {
    asm volatile("cp.async.wait_group 1;\n");
}
__device__ __forceinline__ void ldsm4(unsigned r[4], const void* p) {
    unsigned a = smem_u32(p);
    asm volatile("ldmatrix.sync.aligned.m8n8.x4.shared.b16 {%0,%1,%2,%3}, [%4];\n"
                 : "=r"(r[0]), "=r"(r[1]), "=r"(r[2]), "=r"(r[3]) : "r"(a));
}
__device__ __forceinline__ void mma16816(float d[4], const unsigned a[4],
                                         unsigned b0, unsigned b1) {
    asm volatile("mma.sync.aligned.m16n8k16.row.col.f32.bf16.bf16.f32 "
                 "{%0,%1,%2,%3}, {%4,%5,%6,%7}, {%8,%9}, {%0,%1,%2,%3};\n"
                 : "+f"(d[0]), "+f"(d[1]), "+f"(d[2]), "+f"(d[3])
                 : "r"(a[0]), "r"(a[1]), "r"(a[2]), "r"(a[3]), "r"(b0), "r"(b1));
}
__device__ __forceinline__ unsigned short bfbits(__nv_bfloat16 h) {
    return ((__nv_bfloat16_raw)h).x;
}

// ---------------------------------------------------------------------------
// fp32 -> (hi, lo) bf16 split. x = hi + lo + O(2^-16 |x|).
// ---------------------------------------------------------------------------
__global__ __launch_bounds__(256) void cvt_hilo(
    const float* __restrict__ x, __nv_bfloat16* __restrict__ hi,
    __nv_bfloat16* __restrict__ lo, int n4)
{
    int i = blockIdx.x * blockDim.x + threadIdx.x;
    if (i >= n4) return;
    float4 xv = ((const float4*)x)[i];
    float xs[4] = {xv.x, xv.y, xv.z, xv.w};
    unsigned short hb[4], lb[4];
#pragma unroll
    for (int j = 0; j < 4; ++j) {
        __nv_bfloat16 h = __float2bfloat16(xs[j]);
        float r = xs[j] - __bfloat162float(h);   // exact residual
        __nv_bfloat16 l = __float2bfloat16(r);
        hb[j] = bfbits(h);
        lb[j] = bfbits(l);
    }
    uint2 uh = make_uint2(hb[0] | ((unsigned)hb[1] << 16),
                          hb[2] | ((unsigned)hb[3] << 16));
    uint2 ul = make_uint2(lb[0] | ((unsigned)lb[1] << 16),
                          lb[2] | ((unsigned)lb[3] << 16));
    ((uint2*)hi)[i] = uh;
    ((uint2*)lo)[i] = ul;
}

// ---------------------------------------------------------------------------
// GEMM1 (round-13, unchanged): qkgv[M,512] = act( A @ W^T + bias )
// bf16 hi/lo split, 3-term mma.sync, CTA tile 128m x 256n, BK=32.
// ---------------------------------------------------------------------------
#define G1_STRIDE 40
#define G1_PLANE_A (128 * G1_STRIDE)
#define G1_PLANE_W (256 * G1_STRIDE)
#define G1_STAGE  (2 * G1_PLANE_A + 2 * G1_PLANE_W)
#define G1_SMEM   (3 * G1_STAGE * 2)

__global__ __launch_bounds__(256) void gemm1_mma(
    const __nv_bfloat16* __restrict__ Ah, const __nv_bfloat16* __restrict__ Al,
    const __nv_bfloat16* __restrict__ Wh, const __nv_bfloat16* __restrict__ Wl,
    const float* __restrict__ bias, float* __restrict__ C)
{
    extern __shared__ __nv_bfloat16 sm[];
    const int tid  = threadIdx.x;
    const int m0   = blockIdx.y << 7;
    const int n0   = blockIdx.x << 8;
    const int lane = tid & 31;
    const int warp = tid >> 5;
    const int wm   = (warp & 3) << 5;
    const int wn   = (warp >> 2) << 7;

    const __nv_bfloat16* srcs[4] = {
        Ah + (size_t)m0 * HH, Al + (size_t)m0 * HH,
        Wh + (size_t)n0 * HH, Wl + (size_t)n0 * HH };
    const int poff[4]  = {0, G1_PLANE_A, 2 * G1_PLANE_A, 2 * G1_PLANE_A + G1_PLANE_W};

    auto issue = [&](int kt, int st) {
        __nv_bfloat16* sb = sm + st * G1_STAGE;
#pragma unroll
        for (int h = 0; h < 12; ++h) {
            int c    = tid + (h << 8);
            int grow = c >> 2;
            int col  = (c & 3) << 3;
            int p    = (grow < 256) ? (grow >> 7) : (2 + ((grow - 256) >> 8));
            int r    = (grow < 256) ? (grow & 127) : ((grow - 256) & 255);
            cp16(sb + poff[p] + r * G1_STRIDE + col,
                 srcs[p] + (size_t)r * HH + kt * 32 + col);
        }
        cp_commit();
    };

    float acc[2][16][4];
#pragma unroll
    for (int im = 0; im < 2; ++im)
#pragma unroll
        for (int j = 0; j < 16; ++j)
#pragma unroll
            for (int r = 0; r < 4; ++r) acc[im][j][r] = 0.f;

    issue(0, 0);
    issue(1, 1);

    const int arow  = lane & 15;
    const int acolb = (lane >> 4) << 3;
    const int brow  = ((lane & 16) >> 1) + (lane & 7);
    const int bcolb = ((lane >> 3) & 1) << 3;

    const int nk = HH / 32;
    for (int kt = 0; kt < nk; ++kt) {
        cp_wait1();
        __syncthreads();
        const __nv_bfloat16* st  = sm + (kt % 3) * G1_STAGE;
        const __nv_bfloat16* sAh = st;
        const __nv_bfloat16* sAl = st + G1_PLANE_A;
        const __nv_bfloat16* sWh = st + 2 * G1_PLANE_A;
        const __nv_bfloat16* sWl = st + 2 * G1_PLANE_A + G1_PLANE_W;
#pragma unroll
        for (int ks = 0; ks < 2; ++ks) {
            const int ko = ks << 4;
            unsigned aH[2][4], aL[2][4];
#pragma unroll
            for (int im = 0; im < 2; ++im) {
                int r = wm + (im << 4) + arow;
                ldsm4(aH[im], sAh + r * G1_STRIDE + ko + acolb);
                ldsm4(aL[im], sAl + r * G1_STRIDE + ko + acolb);
            }
#pragma unroll
            for (int ng = 0; ng < 8; ++ng) {
                int r = wn + (ng << 4) + brow;
                unsigned bh[4], bl[4];
                ldsm4(bh, sWh + r * G1_STRIDE + ko + bcolb);
                ldsm4(bl, sWl + r * G1_STRIDE + ko + bcolb);
#pragma unroll
                for (int im = 0; im < 2; ++im) {
                    mma16816(acc[im][ng * 2],     aH[im], bh[0], bh[1]);
                    mma16816(acc[im][ng * 2 + 1], aH[im], bh[2], bh[3]);
                    mma16816(acc[im][ng * 2],     aH[im], bl[0], bl[1]);
                    mma16816(acc[im][ng * 2 + 1], aH[im], bl[2], bl[3]);
                    mma16816(acc[im][ng * 2],     aL[im], bh[0], bh[1]);
                    mma16816(acc[im][ng * 2 + 1], aL[im], bh[2], bh[3]);
                }
            }
        }
        if (kt + 2 < nk) issue(kt + 2, (kt + 2) % 3);
        else             cp_commit();
    }

    const int nblk = (n0 + wn) >> 7;
    const int act  = (nblk == 0) ? 0 : ((nblk == 3) ? 2 : 1);
    const int r0     = m0 + wm + (lane >> 2);
    const int c0base = n0 + wn + ((lane & 3) << 1);
#pragma unroll
    for (int j = 0; j < 16; ++j) {
        int col = c0base + (j << 3);
        float b0 = bias[col], b1 = bias[col + 1];
#pragma unroll
        for (int im = 0; im < 2; ++im) {
            int rb = r0 + (im << 4);
            float v0 = acc[im][j][0] + b0, v1 = acc[im][j][1] + b1;
            float v2 = acc[im][j][2] + b0, v3 = acc[im][j][3] + b1;
            if (act == 1) {
                v0 = 1.f / (1.f + __expf(-v0)); v1 = 1.f / (1.f + __expf(-v1));
                v2 = 1.f / (1.f + __expf(-v2)); v3 = 1.f / (1.f + __expf(-v3));
            } else if (act == 2) {
                v0 = tanhf(v0); v1 = tanhf(v1); v2 = tanhf(v2); v3 = tanhf(v3);
            }
            *(float2*)(C + (size_t)rb * PP + col)       = make_float2(v0, v1);
            *(float2*)(C + (size_t)(rb + 8) * PP + col) = make_float2(v2, v3);
        }
    }
}

// ---------------------------------------------------------------------------
// Scan kernel A: segment-parallel local scan (exact decomposition).
// Grid (vslice=8, b=16, seg=32) = 4096 CTAs, 128 threads (R15 layout:
// warp w = v-quad, lane l = k's 4l..4l+3, state c[4][4], c0 = 0).
// Emits: o_local -> obuf; local final state -> Sbuf[b][seg][k][v];
// vs==0/warp0 also emits P_t = q_t (*) cumprod(g) -> Pbuf[b][t][k] and the
// segment gate-total -> Gtot[b][seg][k]. Cumprod only shrinks; fp32
// underflow -> 0 is the mathematically correct truncation.
// ---------------------------------------------------------------------------
#define SC_GROUPS 3
#define SC_GS     8
#define SC_NGRP   (LS / SC_GS)             // 16 groups per segment

__global__ __launch_bounds__(128) void scan_seg(
    const float* __restrict__ qkgv, float* __restrict__ obuf,
    float* __restrict__ Pbuf, float* __restrict__ Sbuf,
    float* __restrict__ Gtot)
{
    const int vs  = blockIdx.x;          // v-slice (16 wide)
    const int b   = blockIdx.y;
    const int seg = blockIdx.z;
    const int v0  = vs << 4;
    const int t0  = seg * LS;
    const int tid = threadIdx.x;
    const int w   = tid >> 5;
    const int l   = tid & 31;
    const int k0  = l << 2;
    const int vb  = w << 2;

    __shared__ float s[SC_GROUPS * SC_GS][400];

    const float* base = qkgv + ((size_t)b * TT + t0) * PP;
    float* ob = obuf + ((size_t)b * TT + t0) * VV + v0 + vb;
    const bool pwr = (vs == 0 && w == 0);   // P-writer warp (covers all 128 k)

    float c[4][4];
#pragma unroll
    for (int i = 0; i < 4; ++i)
#pragma unroll
        for (int j = 0; j < 4; ++j) c[i][j] = 0.f;
    float cg[4] = {1.f, 1.f, 1.f, 1.f};

    const bool cpr = (tid < 100);
    const int goff = (tid < 96) ? (tid << 2) : (384 + v0 + ((tid - 96) << 2));
    const int soff = (tid < 96) ? (tid << 2) : (384 + ((tid - 96) << 2));

    auto issue_group = [&](int g) {
        if (cpr) {
            const int sb = (g % SC_GROUPS) * SC_GS;
            const float* p = base + (size_t)(g * SC_GS) * PP + goff;
#pragma unroll
            for (int i = 0; i < SC_GS; ++i)
                cp16(&s[sb + i][soff], p + (size_t)i * PP);
        }
        cp_commit();
    };

    issue_group(0);
    issue_group(1);

    for (int g = 0; g < SC_NGRP; ++g) {
        cp_wait1();
        __syncthreads();
        if (g + 2 < SC_NGRP) issue_group(g + 2);
        else                 cp_commit();

        const int sb = (g % SC_GROUPS) * SC_GS;

        float a[SC_GS][4];
#pragma unroll
        for (int i = 0; i < SC_GS; ++i) {
            const float* st = s[sb + i];
            float4 q  = *(const float4*)&st[k0];
            float4 kk = *(const float4*)&st[128 + k0];
            float4 gg = *(const float4*)&st[256 + k0];
            float4 vv = *(const float4*)&st[384 + vb];
            const float qx[4] = {q.x, q.y, q.z, q.w};
            const float kx[4] = {kk.x, kk.y, kk.z, kk.w};
            const float gx[4] = {gg.x, gg.y, gg.z, gg.w};
            const float vx[4] = {vv.x, vv.y, vv.z, vv.w};

            if (pwr) {   // uniform per warp
#pragma unroll
                for (int j = 0; j < 4; ++j) cg[j] *= gx[j];
                *(float4*)&Pbuf[((size_t)b * TT + t0 + g * SC_GS + i) * KK + k0] =
                    make_float4(qx[0] * cg[0], qx[1] * cg[1],
                                qx[2] * cg[2], qx[3] * cg[3]);
            }

#pragma unroll
            for (int ii = 0; ii < 4; ++ii)
#pragma unroll
                for (int j = 0; j < 4; ++j)
                    c[ii][j] = fmaf(c[ii][j], gx[ii], kx[ii] * vx[j]);

#pragma unroll
            for (int j = 0; j < 4; ++j) {
                float p = c[0][j] * qx[0];
                p = fmaf(c[1][j], qx[1], p);
                p = fmaf(c[2][j], qx[2], p);
                p = fmaf(c[3][j], qx[3], p);
                a[i][j] = p;
            }
        }

#pragma unroll
        for (int d = 1; d < 32; d <<= 1) {
#pragma unroll
            for (int i = 0; i < SC_GS; ++i)
#pragma unroll
                for (int j = 0; j < 4; ++j)
                    a[i][j] += __shfl_xor_sync(0xffffffffu, a[i][j], d);
        }
        if (l == 0) {
            const size_t t8 = (size_t)(g * SC_GS) * VV;
#pragma unroll
            for (int i = 0; i < SC_GS; ++i)
                *(float4*)&ob[t8 + (size_t)i * VV] =
                    make_float4(a[i][0], a[i][1], a[i][2], a[i][3]);
        }
    }

    // local final state -> Sbuf[b][seg][k][v]
#pragma unroll
    for (int i = 0; i < 4; ++i)
        *(float4*)&Sbuf[(((size_t)b * NSEG + seg) * KK + (k0 + i)) * VV + v0 + vb] =
            make_float4(c[i][0], c[i][1], c[i][2], c[i][3]);
    if (pwr)
        *(float4*)&Gtot[((size_t)b * NSEG + seg) * KK + k0] =
            make_float4(cg[0], cg[1], cg[2], cg[3]);
}

// ---------------------------------------------------------------------------
// Scan kernel B: serial compose of segment states (tiny).
// Grid (vslice=8, b=16), 256 threads. Thread: k = tid>>1, v half-row of 8.
// C0[b][j] = state before segment j (C0[b][0] = 0); c_final -> cfin.
// ---------------------------------------------------------------------------
__global__ __launch_bounds__(256) void compose_seg(
    const float* __restrict__ Sbuf, const float* __restrict__ Gtot,
    float* __restrict__ C0b, float* __restrict__ cfin)
{
    const int vs = blockIdx.x, b = blockIdx.y;
    const int v0 = vs << 4;
    const int t  = threadIdx.x;
    const int k  = t >> 1;
    const int vh = (t & 1) << 3;

    float c0[8];
#pragma unroll
    for (int i = 0; i < 8; ++i) c0[i] = 0.f;

    for (int j = 0; j < NSEG; ++j) {
        const size_t bj = (((size_t)b * NSEG + j) * KK + k) * VV + v0 + vh;
        *(float4*)&C0b[bj]     = make_float4(c0[0], c0[1], c0[2], c0[3]);
        *(float4*)&C0b[bj + 4] = make_float4(c0[4], c0[5], c0[6], c0[7]);
        const float gt = Gtot[((size_t)b * NSEG + j) * KK + k];
        float4 s0 = *(const float4*)&Sbuf[bj];
        float4 s1 = *(const float4*)&Sbuf[bj + 4];
        c0[0] = fmaf(c0[0], gt, s0.x);  c0[1] = fmaf(c0[1], gt, s0.y);
        c0[2] = fmaf(c0[2], gt, s0.z);  c0[3] = fmaf(c0[3], gt, s0.w);
        c0[4] = fmaf(c0[4], gt, s1.x);  c0[5] = fmaf(c0[5], gt, s1.y);
        c0[6] = fmaf(c0[6], gt, s1.z);  c0[7] = fmaf(c0[7], gt, s1.w);
    }
    const size_t fb = ((size_t)b * KK + k) * VV + v0 + vh;
    *(float4*)&cfin[fb]     = make_float4(c0[0], c0[1], c0[2], c0[3]);
    *(float4*)&cfin[fb + 4] = make_float4(c0[4], c0[5], c0[6], c0[7]);
}

// ---------------------------------------------------------------------------
// Scan kernel C: fixup  obuf[t,v] += sum_k P[t,k] * C0[seg(t)][k,v].
// Grid (seg=32, b=16), 256 threads, 128x128x128 fp32 GEMM with += epilogue.
// ---------------------------------------------------------------------------
__global__ __launch_bounds__(256) void fixup_gemm(
    const float* __restrict__ Pbuf, const float* __restrict__ C0b,
    float* __restrict__ obuf)
{
    __shared__ float As[32][132];   // [k][t]
    __shared__ float Bs[32][132];   // [k][v]

    const int seg = blockIdx.x, b = blockIdx.y;
    const int tid = threadIdx.x;
    const float* P0 = Pbuf + ((size_t)b * TT + seg * LS) * KK;          // [t][k]
    const float* B0 = C0b + (((size_t)b * NSEG + seg) * KK) * (size_t)VV; // [k][v]
    float* O0 = obuf + ((size_t)b * TT + seg * LS) * VV;

    const int ty  = tid >> 4;
    const int tx  = tid & 15;
    const int ar0 = ty << 2;       // t
    const int bc0 = tx << 2;       // v

    float acc[8][8];
#pragma unroll
    for (int i = 0; i < 8; ++i)
#pragma unroll
        for (int j = 0; j < 8; ++j) acc[i][j] = 0.f;

    for (int kt = 0; kt < 4; ++kt) {
        // A: 128 t x 32 k, transpose into As[k][t]
#pragma unroll
        for (int p = 0; p < 4; ++p) {
            int tr = (tid >> 3) + (p << 5);
            int kc = (tid & 7) << 2;
            float4 va = *(const float4*)&P0[(size_t)tr * KK + (kt << 5) + kc];
            As[kc + 0][tr] = va.x;
            As[kc + 1][tr] = va.y;
            As[kc + 2][tr] = va.z;
            As[kc + 3][tr] = va.w;
        }
        // B: 32 k x 128 v, direct
#pragma unroll
        for (int p = 0; p < 4; ++p) {
            int kr = (tid >> 5) + (p << 3);
            int vc = (tid & 31) << 2;
            *(float4*)&Bs[kr][vc] =
                *(const float4*)&B0[(size_t)((kt << 5) + kr) * VV + vc];
        }
        __syncthreads();
#pragma unroll
        for (int kk = 0; kk < 32; ++kk) {
            float4 a0 = *(const float4*)&As[kk][ar0];
            float4 a1 = *(const float4*)&As[kk][64 + ar0];
            float4 b0 = *(const float4*)&Bs[kk][bc0];
            float4 b1 = *(const float4*)&Bs[kk][64 + bc0];
            float af[8] = {a0.x,a0.y,a0.z,a0.w,a1.x,a1.y,a1.z,a1.w};
            float bf[8] = {b0.x,b0.y,b0.z,b0.w,b1.x,b1.y,b1.z,b1.w};
#pragma unroll
            for (int i = 0; i < 8; ++i)
#pragma unroll
                for (int j = 0; j < 8; ++j)
                    acc[i][j] = fmaf(af[i], bf[j], acc[i][j]);
        }
        __syncthreads();
    }

#pragma unroll
    for (int i = 0; i < 8; ++i) {
        int tg = (i < 4) ? (ar0 + i) : (64 + ar0 + (i - 4));
        float* row = O0 + (size_t)tg * VV;
#pragma unroll
        for (int h = 0; h < 2; ++h) {
            int vc = (h == 0) ? bc0 : (64 + bc0);
            float4 o = *(float4*)&row[vc];
            o.x += acc[i][h * 4 + 0];  o.y += acc[i][h * 4 + 1];
            o.z += acc[i][h * 4 + 2];  o.w += acc[i][h * 4 + 3];
            *(float4*)&row[vc] = o;
        }
    }
}

// ---------------------------------------------------------------------------
// GEMM2 (small): fp32 SIMT TN GEMM, 128x128 tile, BK=16.
// ---------------------------------------------------------------------------
__global__ __launch_bounds__(256) void gemm_tn(
    const float* __restrict__ A, const float* __restrict__ W,
    const float* __restrict__ bias, float* __restrict__ C,
    int M, int N, int Kd)
{
    __shared__ float As[2][16][136];
    __shared__ float Bs[2][16][136];

    const int tid = threadIdx.x;
    const int m0 = blockIdx.y << 7;
    const int n0 = blockIdx.x << 7;
    const int lr = tid >> 1;
    const int lc = (tid & 1) << 3;

    const float* Aptr = A + (size_t)(m0 + lr) * Kd + lc;
    const float* Wptr = W + (size_t)(n0 + lr) * Kd + lc;

    {
        float4 a0 = *(const float4*)Aptr;
        float4 a1 = *(const float4*)(Aptr + 4);
        float4 b0 = *(const float4*)Wptr;
        float4 b1 = *(const float4*)(Wptr + 4);
#pragma unroll
        for (int cc = 0; cc < 4; ++cc) {
            As[0][lc + cc][lr]     = ((const float*)&a0)[cc];
            As[0][lc + 4 + cc][lr] = ((const float*)&a1)[cc];
            Bs[0][lc + cc][lr]     = ((const float*)&b0)[cc];
            Bs[0][lc + 4 + cc][lr] = ((const float*)&b1)[cc];
        }
    }
    __syncthreads();

    const int ty  = tid >> 4;
    const int tx  = tid & 15;
    const int ar0 = ty << 2;
    const int bc0 = tx << 2;

    float acc[8][8];
#pragma unroll
    for (int i = 0; i < 8; ++i)
#pragma unroll
        for (int j = 0; j < 8; ++j) acc[i][j] = 0.f;

    const int nk = Kd >> 4;
    for (int kt = 0; kt < nk; ++kt) {
        const int buf = kt & 1;
        float4 pa0, pa1, pb0, pb1;
        const bool pf = (kt + 1) < nk;
        if (pf) {
            const float* Ap = Aptr + ((kt + 1) << 4);
            const float* Wp = Wptr + ((kt + 1) << 4);
            pa0 = *(const float4*)Ap;  pa1 = *(const float4*)(Ap + 4);
            pb0 = *(const float4*)Wp;  pb1 = *(const float4*)(Wp + 4);
        }
#pragma unroll
        for (int kk = 0; kk < 16; ++kk) {
            float4 a0 = *(const float4*)&As[buf][kk][ar0];
            float4 a1 = *(const float4*)&As[buf][kk][64 + ar0];
            float4 b0 = *(const float4*)&Bs[buf][kk][bc0];
            float4 b1 = *(const float4*)&Bs[buf][kk][64 + bc0];
            float af[8] = {a0.x,a0.y,a0.z,a0.w,a1.x,a1.y,a1.z,a1.w};
            float bf[8] = {b0.x,b0.y,b0.z,b0.w,b1.x,b1.y,b1.z,b1.w};
#pragma unroll
            for (int i = 0; i < 8; ++i)
#pragma unroll
                for (int j = 0; j < 8; ++j)
                    acc[i][j] = fmaf(af[i], bf[j], acc[i][j]);
        }
        if (pf) {
            const int nb = buf ^ 1;
#pragma unroll
            for (int cc = 0; cc < 4; ++cc) {
                As[nb][lc + cc][lr]     = ((const float*)&pa0)[cc];
                As[nb][lc + 4 + cc][lr] = ((const float*)&pa1)[cc];
                Bs[nb][lc + cc][lr]     = ((const float*)&pb0)[cc];
                Bs[nb][lc + 4 + cc][lr] = ((const float*)&pb1)[cc];
            }
        }
        __syncthreads();
    }

    float bv[8];
#pragma unroll
    for (int j = 0; j < 8; ++j) {
        int n = n0 + ((j < 4) ? (bc0 + j) : (64 + bc0 + (j - 4)));
        bv[j] = bias[n];
    }
#pragma unroll
    for (int i = 0; i < 8; ++i) {
        int m = m0 + ((i < 4) ? (ar0 + i) : (64 + ar0 + (i - 4)));
        float o[8];
#pragma unroll
        for (int j = 0; j < 8; ++j) o[j] = acc[i][j] + bv[j];
        float* cp = C + (size_t)m * N + n0;
        *(float4*)(cp + bc0)      = make_float4(o[0], o[1], o[2], o[3]);
        *(float4*)(cp + 64 + bc0) = make_float4(o[4], o[5], o[6], o[7]);
    }
}

// ---------------------------------------------------------------------------
extern "C" void kernel_launch(void* const* d_in, const int* in_sizes, int n_in,
                              void* d_out, int out_size)
{
    const float* hidden = (const float*)d_in[0];
    const float* W_proj = (const float*)d_in[1];
    const float* b_proj = (const float*)d_in[2];
    const float* W_out  = (const float*)d_in[3];
    const float* b_out  = (const float*)d_in[4];
    float* out = (float*)d_out;

    float *qkgv, *obuf, *cdump;
    __nv_bfloat16 *ahi, *alo, *whi, *wlo;
    cudaGetSymbolAddress((void**)&qkgv,  g_qkgv);
    cudaGetSymbolAddress((void**)&obuf,  g_obuf);
    cudaGetSymbolAddress((void**)&cdump, g_cdump);
    cudaGetSymbolAddress((void**)&ahi,   g_ahi);
    cudaGetSymbolAddress((void**)&alo,   g_alo);
    cudaGetSymbolAddress((void**)&whi,   g_whi);
    cudaGetSymbolAddress((void**)&wlo,   g_wlo);

    const size_t out_main = (size_t)BB * TT * OO;
    const size_t out_full = out_main + (size_t)BB * KK * VV;
    float* cfin = ((size_t)out_size >= out_full) ? (out + out_main) : cdump;

    // scan scratch reuses g_ahi (dead after gemm1; stream order guarantees)
    float* scr  = (float*)ahi;                       // 33.5M floats capacity
    float* Pbuf = scr;                               //  8.4M floats
    float* Sbuf = Pbuf + (size_t)BB * TT * KK;       //  8.4M
    float* C0b  = Sbuf + (size_t)BB * NSEG * KK * VV;//  8.4M
    float* Gt   = C0b  + (size_t)BB * NSEG * KK * VV;//  65K

    // 0) fp32 -> bf16 hi/lo splits
    {
        int n4 = (MM * HH) / 4;
        cvt_hilo<<<(n4 + 255) / 256, 256>>>(hidden, ahi, alo, n4);
        int w4 = (PP * HH) / 4;
        cvt_hilo<<<(w4 + 255) / 256, 256>>>(W_proj, whi, wlo, w4);
    }
    // 1) fused projection GEMM + activations
    {
        cudaFuncSetAttribute(gemm1_mma,
                             cudaFuncAttributeMaxDynamicSharedMemorySize, G1_SMEM);
        dim3 grid(PP / 256, MM / 128);
        gemm1_mma<<<grid, 256, G1_SMEM>>>(ahi, alo, whi, wlo, b_proj, qkgv);
    }
    // 2a) segment-parallel local scans (+ P, S, Gtot)
    {
        dim3 grid(VV / 16, BB, NSEG);                // (8, 16, 32) = 4096 CTAs
        scan_seg<<<grid, 128>>>(qkgv, obuf, Pbuf, Sbuf, Gt);
    }
    // 2b) compose segment-start states + c_final
    {
        dim3 grid(VV / 16, BB);                      // (8, 16)
        compose_seg<<<grid, 256>>>(Sbuf, Gt, C0b, cfin);
    }
    // 2c) fixup: obuf += P * C0
    {
        dim3 grid(NSEG, BB);                         // (32, 16)
        fixup_gemm<<<grid, 256>>>(Pbuf, C0b, obuf);
    }
    // 3) output projection
    {
        dim3 grid(OO / 128, MM / 128);
        gemm_tn<<<grid, 256>>>(obuf, W_out, b_out, out, MM, OO, VV);
    }
}